// round 1
// baseline (speedup 1.0000x reference)
#include <cuda_runtime.h>
#include <cstddef>

// router_20091857011524: fused 4-way router (GB300 sm_103a)
// B=8, T=4096, D=512, K=4, TOP=2.  Tokens N = 32768.
//
// Design: 32 tokens per block (lane-per-token in the logits phase so the
// W_top/W_soft reads are warp-uniform -> single-line L1 hits), m staged
// through padded SMEM in 128-d chunks (conflict-free both directions),
// per-token epilogue (top-2 softmax + softmax + sigmoid blend), then a
// coalesced output pass re-reading m from L2-hot gmem.

#define TPB_TOK 32
#define CHUNK   128
#define NCHUNK  4
#define THREADS 256
// pad request to ~80KB to cap occupancy at 2 blocks/SM (keeps W L1-resident)
#define SMEM_BYTES 81920

// dynamic smem layout (floats):
//   sm   : [4][32][129]   = 16512
//   slog : [8*32][9]      =  2304   (partial logits, pad 9 for bank spread)
//   sw   : [32][4]        =   128
#define SM_OFF_SLOG 16512
#define SM_OFF_SW   18816

__global__ __launch_bounds__(THREADS, 2)
void router_kernel(const float* __restrict__ m0, const float* __restrict__ m1,
                   const float* __restrict__ m2, const float* __restrict__ m3,
                   const float* __restrict__ Wt, const float* __restrict__ bt,
                   const float* __restrict__ Ws, const float* __restrict__ bs,
                   const float* __restrict__ alpha, float* __restrict__ out)
{
    extern __shared__ float smem[];
    float* sm   = smem;
    float* slog = smem + SM_OFF_SLOG;
    float* sw   = smem + SM_OFF_SW;

    const float* mats[4] = {m0, m1, m2, m3};
    const int tokBase = blockIdx.x * TPB_TOK;
    const int tid  = threadIdx.x;
    const int lane = tid & 31;
    const int wrp  = tid >> 5;
    const int tokA = tid >> 3;     // 0..31 (phase A/C token)
    const int jA   = tid & 7;      // 0..7  (phase A/C inner slot)

    float accT[4] = {0.f, 0.f, 0.f, 0.f};
    float accS[4] = {0.f, 0.f, 0.f, 0.f};

    const float4* wt4 = reinterpret_cast<const float4*>(Wt);  // [4][512] float4
    const float4* ws4 = reinterpret_cast<const float4*>(Ws);

    for (int c = 0; c < NCHUNK; c++) {
        const int d0 = c * CHUNK;

        // ---- Phase A: stage m chunk into SMEM (coalesced gmem, conflict-free STS)
        #pragma unroll
        for (int k = 0; k < 4; k++) {
            const float* mk = mats[k] + (size_t)(tokBase + tokA) * 512 + d0;
            float* s = sm + k * (32 * 129) + tokA * 129;
            #pragma unroll
            for (int r = 0; r < 4; r++) {
                const int dc = 4 * jA + 32 * r;
                float4 v = __ldcs(reinterpret_cast<const float4*>(mk + dc));
                s[dc + 0] = v.x; s[dc + 1] = v.y; s[dc + 2] = v.z; s[dc + 3] = v.w;
            }
        }
        __syncthreads();

        // ---- Phase B: lane-per-token logits accumulation; W reads warp-uniform
        #pragma unroll 4
        for (int it = 0; it < 16; it++) {
            const int dc = wrp * 16 + it;   // this warp's d within chunk
            const int d  = d0 + dc;
            const float x0 = sm[0 * 4128 + lane * 129 + dc];
            const float x1 = sm[1 * 4128 + lane * 129 + dc];
            const float x2 = sm[2 * 4128 + lane * 129 + dc];
            const float x3 = sm[3 * 4128 + lane * 129 + dc];
            #pragma unroll
            for (int kp = 0; kp < 4; kp++) {
                float4 a = __ldg(wt4 + kp * 512 + d);
                accT[kp] += x0 * a.x + x1 * a.y + x2 * a.z + x3 * a.w;
                float4 b = __ldg(ws4 + kp * 512 + d);
                accS[kp] += x0 * b.x + x1 * b.y + x2 * b.z + x3 * b.w;
            }
        }
        __syncthreads();   // before next chunk overwrites sm
    }

    // ---- write partial logits, reduce across the 8 warps
    {
        float* sl = slog + (wrp * 32 + lane) * 9;
        #pragma unroll
        for (int kp = 0; kp < 4; kp++) { sl[kp] = accT[kp]; sl[4 + kp] = accS[kp]; }
    }
    __syncthreads();

    // ---- per-token epilogue (one lane per token, warp 0)
    if (tid < 32) {
        const int tok = tid;
        float lt[4], ls[4];
        #pragma unroll
        for (int kp = 0; kp < 4; kp++) { lt[kp] = __ldg(bt + kp); ls[kp] = __ldg(bs + kp); }
        #pragma unroll
        for (int w2 = 0; w2 < 8; w2++) {
            const float* p = slog + (w2 * 32 + tok) * 9;
            #pragma unroll
            for (int kp = 0; kp < 4; kp++) { lt[kp] += p[kp]; ls[kp] += p[4 + kp]; }
        }
        // top-2 (first-index tie semantics like jax top_k)
        int i0 = 0; float v0 = lt[0];
        #pragma unroll
        for (int k = 1; k < 4; k++) if (lt[k] > v0) { v0 = lt[k]; i0 = k; }
        int i1 = -1; float v1 = -3.0e38f;
        #pragma unroll
        for (int k = 0; k < 4; k++) if (k != i0 && lt[k] > v1) { v1 = lt[k]; i1 = k; }
        const float e  = __expf(v1 - v0);
        const float s2 = 1.0f / (1.0f + e);
        const float p0 = s2;          // weight at i0
        const float p1 = e * s2;      // weight at i1
        // softmax over soft logits
        const float mx = fmaxf(fmaxf(ls[0], ls[1]), fmaxf(ls[2], ls[3]));
        float es[4];
        #pragma unroll
        for (int k = 0; k < 4; k++) es[k] = __expf(ls[k] - mx);
        const float inv = 1.0f / (es[0] + es[1] + es[2] + es[3]);
        const float a = 1.0f / (1.0f + __expf(-__ldg(alpha)));
        #pragma unroll
        for (int k = 0; k < 4; k++) {
            const float hard = (k == i0) ? p0 : ((k == i1) ? p1 : 0.0f);
            sw[tok * 4 + k] = a * hard + (1.0f - a) * (es[k] * inv);
        }
    }
    __syncthreads();

    // ---- Phase C: weighted sum, coalesced; m re-read is L2-hot
    {
        const int tok = tokA;
        const float w0 = sw[tok * 4 + 0];
        const float w1 = sw[tok * 4 + 1];
        const float w2 = sw[tok * 4 + 2];
        const float w3 = sw[tok * 4 + 3];
        const size_t rowOff = (size_t)(tokBase + tok) * 512;
        const float4* p0_ = reinterpret_cast<const float4*>(m0 + rowOff);
        const float4* p1_ = reinterpret_cast<const float4*>(m1 + rowOff);
        const float4* p2_ = reinterpret_cast<const float4*>(m2 + rowOff);
        const float4* p3_ = reinterpret_cast<const float4*>(m3 + rowOff);
        float4* po = reinterpret_cast<float4*>(out + rowOff);
        #pragma unroll 4
        for (int r = 0; r < 16; r++) {
            const int f = jA + 8 * r;   // float4 index within the 512-wide row
            float4 va = __ldcs(p0_ + f);
            float4 vb = __ldcs(p1_ + f);
            float4 vc = __ldcs(p2_ + f);
            float4 vd = __ldcs(p3_ + f);
            float4 o;
            o.x = w0 * va.x + w1 * vb.x + w2 * vc.x + w3 * vd.x;
            o.y = w0 * va.y + w1 * vb.y + w2 * vc.y + w3 * vd.y;
            o.z = w0 * va.z + w1 * vb.z + w2 * vc.z + w3 * vd.z;
            o.w = w0 * va.w + w1 * vb.w + w2 * vc.w + w3 * vd.w;
            po[f] = o;
        }
    }
}

extern "C" void kernel_launch(void* const* d_in, const int* in_sizes, int n_in,
                              void* d_out, int out_size)
{
    const float* m0    = (const float*)d_in[0];
    const float* m1    = (const float*)d_in[1];
    const float* m2    = (const float*)d_in[2];
    const float* m3    = (const float*)d_in[3];
    const float* W_top = (const float*)d_in[4];
    const float* b_top = (const float*)d_in[5];
    const float* W_sft = (const float*)d_in[6];
    const float* b_sft = (const float*)d_in[7];
    const float* alpha = (const float*)d_in[8];
    float* out = (float*)d_out;

    const int ntok = in_sizes[0] / 512;       // 32768
    const int grid = ntok / TPB_TOK;          // 1024

    cudaFuncSetAttribute(router_kernel,
                         cudaFuncAttributeMaxDynamicSharedMemorySize, SMEM_BYTES);
    router_kernel<<<grid, THREADS, SMEM_BYTES>>>(m0, m1, m2, m3,
                                                 W_top, b_top, W_sft, b_sft,
                                                 alpha, out);
}

// round 3
// speedup vs baseline: 1.4351x; 1.4351x over previous
#include <cuda_runtime.h>
#include <cstddef>

// router_20091857011524: fused 4-way router (GB300 sm_103a) — R3
// B=8, T=4096, D=512, K=4, TOP=2.  Tokens N = 32768.
//
// 32 tokens/block, 256 threads (8 warps), d chunked by 64.
// Phase A: m chunk -> SMEM, stride-68 padding (16B aligned AND conflict-free).
// W chunk (64 dims x 8 outs x 4 mats) staged to SMEM per chunk; phase-B reads
// it as warp-uniform broadcast LDS.128 (2cyc floor vs 4cyc LDG).
// Phase B: lane-per-token, warp owns 8 dims/chunk, vector LDS.128 x reads.
// Epilogue: top-2 softmax + soft softmax + sigmoid blend per token.
// Phase C: coalesced weighted sum; m re-read L2-hot (__ldcs last touch).

#define THREADS 256
#define TPB_TOK 32
#define CHUNK   64
#define NCHUNK  8

// smem layout (floats):
//   xs   : [4][32][68]  = 8704   (stride 68: aligned + conflict-free)
//   wsm  : [64][9] f4   = 2304   (9 f4/dim: pad kills staging STS conflicts)
//   slog : [8*32][9]    = 2304
//   sw   : [32][4]      =  128
#define SM_OFF_W    8704
#define SM_OFF_SLOG 11008
#define SM_OFF_SW   13312
#define SMEM_FLOATS 13440
#define SMEM_BYTES  (SMEM_FLOATS * 4)

__global__ __launch_bounds__(THREADS, 4)
void router_kernel(const float* __restrict__ m0, const float* __restrict__ m1,
                   const float* __restrict__ m2, const float* __restrict__ m3,
                   const float* __restrict__ Wt, const float* __restrict__ bt,
                   const float* __restrict__ Ws, const float* __restrict__ bs,
                   const float* __restrict__ alpha, float* __restrict__ out)
{
    extern __shared__ float smem[];
    float*  xs   = smem;
    float4* wsm4 = reinterpret_cast<float4*>(smem + SM_OFF_W);
    float*  slog = smem + SM_OFF_SLOG;
    float*  sw   = smem + SM_OFF_SW;

    const float* mats[4] = {m0, m1, m2, m3};
    const int tokBase = blockIdx.x * TPB_TOK;
    const int tid  = threadIdx.x;
    const int lane = tid & 31;
    const int wrp  = tid >> 5;
    const int tokA = tid >> 3;     // 0..31 (phase A/C token)
    const int jA   = tid & 7;      // 0..7  (phase A/C inner slot)

    float acc[8];
    #pragma unroll
    for (int o = 0; o < 8; o++) acc[o] = 0.f;

    const float4* wt4 = reinterpret_cast<const float4*>(Wt);  // [4][512] float4
    const float4* ws4 = reinterpret_cast<const float4*>(Ws);
    const float4* xs4 = reinterpret_cast<const float4*>(xs);

    for (int c = 0; c < NCHUNK; c++) {
        const int d0 = c * CHUNK;

        // ---- stage W chunk: wsm[d][o] = 4 mat-weights for (dim d0+d, out o)
        // o in [0,4): W_top rows; o in [4,8): W_soft rows. Coalesced LDG.
        #pragma unroll
        for (int rep = 0; rep < 2; rep++) {
            const int i  = tid + rep * 256;   // 0..511
            const int o  = i >> 6;            // 0..7
            const int dd = i & 63;            // 0..63
            float4 w = (o < 4) ? __ldg(wt4 + o * 512 + d0 + dd)
                               : __ldg(ws4 + (o - 4) * 512 + d0 + dd);
            wsm4[dd * 9 + o] = w;
        }

        // ---- stage m chunk into SMEM (batched loads, then aligned STS.128)
        {
            float4 v[4][2];
            #pragma unroll
            for (int k = 0; k < 4; k++) {
                const float* mk = mats[k] + (size_t)(tokBase + tokA) * 512 + d0;
                #pragma unroll
                for (int r = 0; r < 2; r++)
                    v[k][r] = *reinterpret_cast<const float4*>(mk + 4 * (jA + 8 * r));
            }
            #pragma unroll
            for (int k = 0; k < 4; k++) {
                float* s = xs + k * (32 * 68) + tokA * 68;
                #pragma unroll
                for (int r = 0; r < 2; r++)
                    *reinterpret_cast<float4*>(s + 4 * (jA + 8 * r)) = v[k][r];
            }
        }
        __syncthreads();

        // ---- Phase B: lane = token; warp owns dims [wrp*8, wrp*8+8) of chunk
        #pragma unroll
        for (int g = 0; g < 2; g++) {
            const int dc = wrp * 2 + g;                 // float4-group in chunk (0..15)
            float4 x0 = xs4[0 * 544 + lane * 17 + dc];  // 544=2176/4, 17=68/4
            float4 x1 = xs4[1 * 544 + lane * 17 + dc];
            float4 x2 = xs4[2 * 544 + lane * 17 + dc];
            float4 x3 = xs4[3 * 544 + lane * 17 + dc];
            const float* xf0 = reinterpret_cast<const float*>(&x0);
            const float* xf1 = reinterpret_cast<const float*>(&x1);
            const float* xf2 = reinterpret_cast<const float*>(&x2);
            const float* xf3 = reinterpret_cast<const float*>(&x3);
            const int dloc = (wrp * 8 + g * 4);         // dim-in-chunk of x0.x
            #pragma unroll
            for (int j = 0; j < 4; j++) {
                #pragma unroll
                for (int o = 0; o < 8; o++) {
                    float4 w = wsm4[(dloc + j) * 9 + o];   // warp-uniform broadcast
                    acc[o] += xf0[j] * w.x + xf1[j] * w.y + xf2[j] * w.z + xf3[j] * w.w;
                }
            }
        }
        __syncthreads();   // before next chunk overwrites smem
    }

    // ---- write partial logits, reduce across the 8 warps
    {
        float* sl = slog + (wrp * 32 + lane) * 9;
        #pragma unroll
        for (int o = 0; o < 8; o++) sl[o] = acc[o];
    }
    __syncthreads();

    // ---- per-token epilogue (one lane per token, warp 0)
    if (tid < 32) {
        const int tok = tid;
        float lt[4], ls[4];
        #pragma unroll
        for (int kp = 0; kp < 4; kp++) { lt[kp] = __ldg(bt + kp); ls[kp] = __ldg(bs + kp); }
        #pragma unroll
        for (int w2 = 0; w2 < 8; w2++) {
            const float* p = slog + (w2 * 32 + tok) * 9;
            #pragma unroll
            for (int kp = 0; kp < 4; kp++) { lt[kp] += p[kp]; ls[kp] += p[4 + kp]; }
        }
        // top-2 (first-index tie semantics like jax top_k)
        int i0 = 0; float v0 = lt[0];
        #pragma unroll
        for (int k = 1; k < 4; k++) if (lt[k] > v0) { v0 = lt[k]; i0 = k; }
        int i1 = -1; float v1 = -3.0e38f;
        #pragma unroll
        for (int k = 0; k < 4; k++) if (k != i0 && lt[k] > v1) { v1 = lt[k]; i1 = k; }
        const float e  = __expf(v1 - v0);
        const float s2 = 1.0f / (1.0f + e);
        const float p0 = s2;
        const float p1 = e * s2;
        // softmax over soft logits
        const float mx = fmaxf(fmaxf(ls[0], ls[1]), fmaxf(ls[2], ls[3]));
        float es[4];
        #pragma unroll
        for (int k = 0; k < 4; k++) es[k] = __expf(ls[k] - mx);
        const float inv = 1.0f / (es[0] + es[1] + es[2] + es[3]);
        const float a = 1.0f / (1.0f + __expf(-__ldg(alpha)));
        #pragma unroll
        for (int k = 0; k < 4; k++) {
            const float hard = (k == i0) ? p0 : ((k == i1) ? p1 : 0.0f);
            sw[tok * 4 + k] = a * hard + (1.0f - a) * (es[k] * inv);
        }
    }
    __syncthreads();

    // ---- Phase C: weighted sum, coalesced; m re-read L2-hot (last touch)
    {
        const int tok = tokA;
        const float w0 = sw[tok * 4 + 0];
        const float w1 = sw[tok * 4 + 1];
        const float w2 = sw[tok * 4 + 2];
        const float w3 = sw[tok * 4 + 3];
        const size_t rowOff = (size_t)(tokBase + tok) * 512;
        const float4* p0_ = reinterpret_cast<const float4*>(m0 + rowOff);
        const float4* p1_ = reinterpret_cast<const float4*>(m1 + rowOff);
        const float4* p2_ = reinterpret_cast<const float4*>(m2 + rowOff);
        const float4* p3_ = reinterpret_cast<const float4*>(m3 + rowOff);
        float4* po = reinterpret_cast<float4*>(out + rowOff);
        #pragma unroll 4
        for (int r = 0; r < 16; r++) {
            const int f = jA + 8 * r;   // float4 index within the 512-wide row
            float4 va = __ldcs(p0_ + f);
            float4 vb = __ldcs(p1_ + f);
            float4 vc = __ldcs(p2_ + f);
            float4 vd = __ldcs(p3_ + f);
            float4 o;
            o.x = w0 * va.x + w1 * vb.x + w2 * vc.x + w3 * vd.x;
            o.y = w0 * va.y + w1 * vb.y + w2 * vc.y + w3 * vd.y;
            o.z = w0 * va.z + w1 * vb.z + w2 * vc.z + w3 * vd.z;
            o.w = w0 * va.w + w1 * vb.w + w2 * vc.w + w3 * vd.w;
            po[f] = o;
        }
    }
}

extern "C" void kernel_launch(void* const* d_in, const int* in_sizes, int n_in,
                              void* d_out, int out_size)
{
    const float* m0    = (const float*)d_in[0];
    const float* m1    = (const float*)d_in[1];
    const float* m2    = (const float*)d_in[2];
    const float* m3    = (const float*)d_in[3];
    const float* W_top = (const float*)d_in[4];
    const float* b_top = (const float*)d_in[5];
    const float* W_sft = (const float*)d_in[6];
    const float* b_sft = (const float*)d_in[7];
    const float* alpha = (const float*)d_in[8];
    float* out = (float*)d_out;

    const int ntok = in_sizes[0] / 512;       // 32768
    const int grid = ntok / TPB_TOK;          // 1024

    cudaFuncSetAttribute(router_kernel,
                         cudaFuncAttributeMaxDynamicSharedMemorySize, SMEM_BYTES);
    router_kernel<<<grid, THREADS, SMEM_BYTES>>>(m0, m1, m2, m3,
                                                 W_top, b_top, W_sft, b_sft,
                                                 alpha, out);
}